// round 8
// baseline (speedup 1.0000x reference)
#include <cuda_runtime.h>
#include <cuda_bf16.h>
#include <cstdint>

#define NN 8192
#define INSZ 256
#define HID 128

// ---------------- device global scratch (allocation-free) ----------------
__device__ __align__(256) __nv_bfloat16 g_Ahi[NN * HID];
__device__ __align__(256) __nv_bfloat16 g_Bhi[NN * HID];
__device__ float g_rowS[NN * 128];           // [i][Jc]  Jc in 0..127
__device__ float g_rowP[NN * 128];
__device__ float g_colS[NN * 64];            // [j][Ic]  Ic in 0..63
__device__ float g_colP[NN * 64];

// ---------------- helpers ----------------
__device__ __forceinline__ uint32_t smem_u32(const void* p) {
    uint32_t a;
    asm("{ .reg .u64 t; cvta.to.shared.u64 t, %1; cvt.u32.u64 %0, t; }" : "=r"(a) : "l"(p));
    return a;
}
__device__ __forceinline__ float ex2f(float x) {
    float y; asm("ex2.approx.ftz.f32 %0, %1;" : "=f"(y) : "f"(x)); return y;
}
__device__ __forceinline__ void prefetchL2(const void* p) {
    asm volatile("prefetch.global.L2 [%0];" :: "l"(p));
}
__device__ __forceinline__ void ldsm4(uint32_t a, uint32_t& r0, uint32_t& r1,
                                      uint32_t& r2, uint32_t& r3) {
    asm volatile("ldmatrix.sync.aligned.m8n8.x4.shared.b16 {%0,%1,%2,%3}, [%4];"
                 : "=r"(r0), "=r"(r1), "=r"(r2), "=r"(r3) : "r"(a));
}
__device__ __forceinline__ void mma16816(float* d, const uint32_t* a, const uint32_t* b) {
    asm volatile("mma.sync.aligned.m16n8k16.row.col.f32.bf16.bf16.f32 "
                 "{%0,%1,%2,%3}, {%4,%5,%6,%7}, {%8,%9}, {%0,%1,%2,%3};"
                 : "+f"(d[0]), "+f"(d[1]), "+f"(d[2]), "+f"(d[3])
                 : "r"(a[0]), "r"(a[1]), "r"(a[2]), "r"(a[3]), "r"(b[0]), "r"(b[1]));
}
__device__ __forceinline__ void cp16(uint32_t dst, const void* src) {
    asm volatile("cp.async.cg.shared.global [%0], [%1], 16;" :: "r"(dst), "l"(src));
}
__device__ __forceinline__ void cp_commit_wait() {
    asm volatile("cp.async.commit_group;\n\tcp.async.wait_group 0;" ::: "memory");
}
__device__ __forceinline__ unsigned long long dup2(float a) {
    unsigned long long r; asm("mov.b64 %0, {%1, %1};" : "=l"(r) : "f"(a)); return r;
}
__device__ __forceinline__ void fma2(unsigned long long& d, unsigned long long a,
                                     unsigned long long b) {
    asm("fma.rn.f32x2 %0, %1, %2, %0;" : "+l"(d) : "l"(a), "l"(b));
}
__device__ __forceinline__ float2 unpk(unsigned long long v) {
    float2 r; asm("mov.b64 {%0, %1}, %2;" : "=f"(r.x), "=f"(r.y) : "l"(v)); return r;
}

// ---------------------------------------------------------------------------
// Kernel 1: projection + L2 norm -> single bf16 output (A pre-scaled 5*log2e).
// grid = (128 row-blocks of 64, 2 inputs), 256 threads.
// ---------------------------------------------------------------------------
#define ZS 68
#define HS 66
#define PROJ_SMEM_FLOATS (64 * ZS + 64 * 128)
#define PROJ_SMEM_BYTES  (PROJ_SMEM_FLOATS * 4)

__global__ void __launch_bounds__(256, 2)
proj_kernel(const float* __restrict__ zA, const float* __restrict__ zB,
            const float* __restrict__ W1, const float* __restrict__ b1,
            const float* __restrict__ W2, const float* __restrict__ b2) {
    const bool isA = (blockIdx.y == 0);
    const float* z = isA ? zA : zB;
    __nv_bfloat16* hiDst = isA ? g_Ahi : g_Bhi;

    extern __shared__ float sm[];
    float* z_s = sm;                 // [64][ZS]
    float* w_s = sm + 64 * ZS;       // [64][128]
    float* h_s = sm;                 // [128][HS] (aliases after phase A)

    const int tid = threadIdx.x;
    const int tx = tid & 15, ty = tid >> 4;
    const int R0 = ty * 4, C0 = tx * 8;
    const int blk = blockIdx.x;
    const float* zblk = z + (size_t)blk * 64 * INSZ;

    unsigned long long acc[4][4];
    #pragma unroll
    for (int i = 0; i < 4; ++i)
        #pragma unroll
        for (int jp = 0; jp < 4; ++jp) acc[i][jp] = 0ull;

    for (int kc = 0; kc < 4; ++kc) {
        __syncthreads();
        #pragma unroll
        for (int it = 0; it < 4; ++it) {
            int e = it * 256 + tid;
            int r = e >> 4, k4 = (e & 15) * 4;
            float4 v = *(const float4*)&zblk[r * INSZ + kc * 64 + k4];
            *(float4*)&z_s[r * ZS + k4] = v;
        }
        #pragma unroll
        for (int it = 0; it < 8; ++it) {
            int e = it * 256 + tid;
            int c4 = (e & 31) * 4, k = e >> 5;
            float4 v = *(const float4*)&W1[(size_t)(kc * 64 + k) * HID + c4];
            *(float4*)&w_s[k * 128 + c4] = v;
        }
        __syncthreads();
        #pragma unroll 4
        for (int k = 0; k < 64; ++k) {
            ulonglong2 bb0 = *(const ulonglong2*)&w_s[k * 128 + C0];
            ulonglong2 bb1 = *(const ulonglong2*)&w_s[k * 128 + C0 + 4];
            #pragma unroll
            for (int i = 0; i < 4; ++i) {
                unsigned long long ad = dup2(z_s[(R0 + i) * ZS + k]);
                fma2(acc[i][0], ad, bb0.x);
                fma2(acc[i][1], ad, bb0.y);
                fma2(acc[i][2], ad, bb1.x);
                fma2(acc[i][3], ad, bb1.y);
            }
        }
    }
    __syncthreads();

    float b1c[8];
    #pragma unroll
    for (int j = 0; j < 8; ++j) b1c[j] = b1[C0 + j];
    #pragma unroll
    for (int i = 0; i < 4; ++i) {
        #pragma unroll
        for (int jp = 0; jp < 4; ++jp) {
            float2 v = unpk(acc[i][jp]);
            float x0 = v.x + b1c[2 * jp];
            float x1 = v.y + b1c[2 * jp + 1];
            x0 = (x0 > 0.0f) ? x0 : (ex2f(fmaxf(x0, -30.0f) * 1.4426950408889634f) - 1.0f);
            x1 = (x1 > 0.0f) ? x1 : (ex2f(fmaxf(x1, -30.0f) * 1.4426950408889634f) - 1.0f);
            h_s[(C0 + 2 * jp)     * HS + R0 + i] = x0;
            h_s[(C0 + 2 * jp + 1) * HS + R0 + i] = x1;
        }
    }
    __syncthreads();

    #pragma unroll
    for (int i = 0; i < 4; ++i)
        #pragma unroll
        for (int jp = 0; jp < 4; ++jp) acc[i][jp] = 0ull;

    #pragma unroll 4
    for (int k = 0; k < 128; ++k) {
        ulonglong2 bb0 = *(const ulonglong2*)&W2[(size_t)k * HID + C0];
        ulonglong2 bb1 = *(const ulonglong2*)&W2[(size_t)k * HID + C0 + 4];
        #pragma unroll
        for (int i = 0; i < 4; ++i) {
            unsigned long long ad = dup2(h_s[k * HS + R0 + i]);
            fma2(acc[i][0], ad, bb0.x);
            fma2(acc[i][1], ad, bb0.y);
            fma2(acc[i][2], ad, bb1.x);
            fma2(acc[i][3], ad, bb1.y);
        }
    }

    float b2c[8];
    #pragma unroll
    for (int j = 0; j < 8; ++j) b2c[j] = b2[C0 + j];

    float x[4][8], ss[4];
    #pragma unroll
    for (int i = 0; i < 4; ++i) {
        float s = 0.0f;
        #pragma unroll
        for (int jp = 0; jp < 4; ++jp) {
            float2 v = unpk(acc[i][jp]);
            float x0 = v.x + b2c[2 * jp];
            float x1 = v.y + b2c[2 * jp + 1];
            x[i][2 * jp] = x0; x[i][2 * jp + 1] = x1;
            s = fmaf(x0, x0, s); s = fmaf(x1, x1, s);
        }
        ss[i] = s;
    }
    #pragma unroll
    for (int m = 1; m < 16; m <<= 1)
        #pragma unroll
        for (int i = 0; i < 4; ++i)
            ss[i] += __shfl_xor_sync(0xffffffffu, ss[i], m);

    const float scl = isA ? 7.2134752044448170f : 1.0f;   // 5 * log2(e) on A
    union { __nv_bfloat16 b[8]; uint4 u; } hv;
    #pragma unroll
    for (int i = 0; i < 4; ++i) {
        float inv = scl / fmaxf(sqrtf(ss[i]), 1e-12f);
        int gRow = blk * 64 + R0 + i;
        #pragma unroll
        for (int j = 0; j < 8; ++j)
            hv.b[j] = __float2bfloat16(x[i][j] * inv);
        *(uint4*)&hiDst[(size_t)gRow * HID + C0] = hv.u;
    }
}

// ---------------------------------------------------------------------------
// Kernel 2: fused sim tile 128(M) x 64(N), single bf16 pass, 3 CTAs/SM.
// pos is read RAW in the epilogue (no pre-pack): each element is consumed by
// exactly 2 tiles; the 512MB DRAM stream hides under the tensor-bound mainloop.
// grid = (J=128, I=64), 256 threads = 8 warps (4 M-bands x 2 N-bands).
// ---------------------------------------------------------------------------
#define SM_A0 0
#define SM_B0 32768
#define SM_ROWS 0
#define SM_ROWP 1024
#define SM_COLS 2048
#define SM_COLP 3072
#define SIM_SMEM_BYTES 49152

__global__ void __launch_bounds__(256, 3) sim_kernel(const int* __restrict__ pos) {
    const int J = blockIdx.x, I = blockIdx.y;
    extern __shared__ char smc[];
    const uint32_t sb = smem_u32(smc);
    const int tid = threadIdx.x;
    const int lane = tid & 31, wid = tid >> 5;
    const int wm = wid & 3, wn = wid >> 2;   // warp tile: rows wm*32..+31, cols wn*32..+31

    // ---- prefetch this tile's pos footprint into L2 (used in epilogue) ----
    {
        // row-term region: pos[I*128 + r][J*64 .. +64), 128 rows x 256B
        int r = tid >> 1;
        prefetchL2(pos + (size_t)(I * 128 + r) * NN + J * 64 + (tid & 1) * 32);
        // col-term region: pos[J*64 + j][I*128 .. +128), 64 rows x 512B
        int j = tid >> 2;
        prefetchL2(pos + (size_t)(J * 64 + j) * NN + I * 128 + (tid & 3) * 32);
    }

    // ---- async-load operand tiles (swizzled: chunk c -> c ^ (r&7)) ----
    {
        const uint4* srcA0 = (const uint4*)(g_Ahi + (size_t)I * 128 * HID);
        const uint4* srcB0 = (const uint4*)(g_Bhi + (size_t)J * 64 * HID);
        #pragma unroll
        for (int it = 0; it < 8; ++it) {
            int e = it * 256 + tid;
            int r = e >> 4, c = e & 15;
            uint32_t so = r * 256 + ((c ^ (r & 7)) << 4);
            cp16(sb + SM_A0 + so, srcA0 + e);
            if (it < 4) cp16(sb + SM_B0 + so, srcB0 + e);
        }
    }
    cp_commit_wait();
    __syncthreads();

    // ---- MMA mainloop (single pass) ----
    float d[2][4][4];
    #pragma unroll
    for (int mt = 0; mt < 2; ++mt)
        #pragma unroll
        for (int nt = 0; nt < 4; ++nt)
            #pragma unroll
            for (int k = 0; k < 4; ++k) d[mt][nt][k] = 0.0f;

    const uint32_t aB0 = sb + SM_A0, bB = sb + SM_B0;

    #pragma unroll
    for (int ks = 0; ks < 8; ++ks) {
        uint32_t bf[4][2];
        #pragma unroll
        for (int np = 0; np < 2; ++np) {
            int l = lane & 7, g = lane >> 3;
            int row = wn * 32 + np * 16 + ((g >> 1) << 3) + l;
            int ch  = ks * 2 + (g & 1);
            ldsm4(bB + row * 256 + ((ch ^ (row & 7)) << 4),
                  bf[2 * np][0], bf[2 * np][1], bf[2 * np + 1][0], bf[2 * np + 1][1]);
        }
        uint32_t af0[2][4];
        #pragma unroll
        for (int mt = 0; mt < 2; ++mt) {
            int row = wm * 32 + mt * 16 + (lane & 15);
            int ch  = ks * 2 + (lane >> 4);
            uint32_t so = row * 256 + ((ch ^ (row & 7)) << 4);
            ldsm4(aB0 + so, af0[mt][0], af0[mt][1], af0[mt][2], af0[mt][3]);
        }
        #pragma unroll
        for (int mt = 0; mt < 2; ++mt)
            #pragma unroll
            for (int nt = 0; nt < 4; ++nt)
                mma16816(d[mt][nt], af0[mt], bf[nt]);
    }
    __syncthreads();   // operand smem reused for reduction buffers

    // ---- epilogue: exp2, then row/col masked reductions with raw pos ----
    #pragma unroll
    for (int mt = 0; mt < 2; ++mt)
        #pragma unroll
        for (int nt = 0; nt < 4; ++nt)
            #pragma unroll
            for (int k = 0; k < 4; ++k)
                d[mt][nt][k] = ex2f(d[mt][nt][k]);

    float* rowSsm = (float*)(smc + SM_ROWS);   // [2 wn][128]
    float* rowPsm = (float*)(smc + SM_ROWP);
    float* colSsm = (float*)(smc + SM_COLS);   // [4 wm][64]
    float* colPsm = (float*)(smc + SM_COLP);

    // row sums: thread covers rows (mt, h); pos[i][j] read as int2 per nt.
    #pragma unroll
    for (int mt = 0; mt < 2; ++mt) {
        #pragma unroll
        for (int h = 0; h < 2; ++h) {
            int iloc = wm * 32 + mt * 16 + h * 8 + (lane >> 2);
            const int2* prow = (const int2*)(pos + (size_t)(I * 128 + iloc) * NN
                                             + J * 64 + wn * 32 + (lane & 3) * 2);
            float s = 0.0f, p = 0.0f;
            #pragma unroll
            for (int nt = 0; nt < 4; ++nt) {
                int2 pv = prow[nt * 4];      // cols nt*8 + (lane&3)*2 (+1)
                float e0 = d[mt][nt][h * 2];
                float e1 = d[mt][nt][h * 2 + 1];
                s += e0 + e1;
                if (pv.x) p += e0;
                if (pv.y) p += e1;
            }
            s += __shfl_xor_sync(0xffffffffu, s, 1);
            s += __shfl_xor_sync(0xffffffffu, s, 2);
            p += __shfl_xor_sync(0xffffffffu, p, 1);
            p += __shfl_xor_sync(0xffffffffu, p, 2);
            if ((lane & 3) == 0) {
                rowSsm[wn * 128 + iloc] = s;
                rowPsm[wn * 128 + iloc] = p;
            }
        }
    }

    // col sums: thread covers cols (nt, b); pos[j][i] read as scalar per (mt,h).
    #pragma unroll
    for (int nt = 0; nt < 4; ++nt) {
        #pragma unroll
        for (int b = 0; b < 2; ++b) {
            int jloc = wn * 32 + nt * 8 + (lane & 3) * 2 + b;
            const int* pcol = pos + (size_t)(J * 64 + jloc) * NN
                              + I * 128 + wm * 32 + (lane >> 2);
            float s = 0.0f, p = 0.0f;
            #pragma unroll
            for (int mt = 0; mt < 2; ++mt)
                #pragma unroll
                for (int h = 0; h < 2; ++h) {
                    int pv = pcol[mt * 16 + h * 8];
                    float e = d[mt][nt][h * 2 + b];
                    s += e;
                    if (pv) p += e;
                }
            s += __shfl_xor_sync(0xffffffffu, s, 4);
            s += __shfl_xor_sync(0xffffffffu, s, 8);
            s += __shfl_xor_sync(0xffffffffu, s, 16);
            p += __shfl_xor_sync(0xffffffffu, p, 4);
            p += __shfl_xor_sync(0xffffffffu, p, 8);
            p += __shfl_xor_sync(0xffffffffu, p, 16);
            if ((lane >> 2) == 0) {
                colSsm[wm * 64 + jloc] = s;
                colPsm[wm * 64 + jloc] = p;
            }
        }
    }
    __syncthreads();

    // partial writes in [i][chunk] layout (finish reads become contiguous)
    if (tid < 128) {
        float rs = rowSsm[tid] + rowSsm[128 + tid];
        float rp = rowPsm[tid] + rowPsm[128 + tid];
        g_rowS[(size_t)(I * 128 + tid) * 128 + J] = rs;
        g_rowP[(size_t)(I * 128 + tid) * 128 + J] = rp;
    } else if (tid < 192) {
        int j = tid - 128;
        float cs = colSsm[j] + colSsm[64 + j] + colSsm[128 + j] + colSsm[192 + j];
        float cp = colPsm[j] + colPsm[64 + j] + colPsm[128 + j] + colPsm[192 + j];
        g_colS[(size_t)(J * 64 + j) * 64 + I] = cs;
        g_colP[(size_t)(J * 64 + j) * 64 + I] = cp;
    }
}

// ---------------------------------------------------------------------------
// Kernel 3: final reduction, 4 threads per row (deterministic, fixed split)
// ---------------------------------------------------------------------------
__global__ void __launch_bounds__(256) finish_kernel(float* __restrict__ out) {
    int g = blockIdx.x * 256 + threadIdx.x;   // grid 128 x 256 = 32768
    int i = g >> 2, q = g & 3;
    const float4* r4s = (const float4*)&g_rowS[(size_t)i * 128];
    const float4* r4p = (const float4*)&g_rowP[(size_t)i * 128];
    const float4* c4s = (const float4*)&g_colS[(size_t)i * 64];
    const float4* c4p = (const float4*)&g_colP[(size_t)i * 64];
    float rs = 0.0f, rp = 0.0f, cs = 0.0f, cp = 0.0f;
    #pragma unroll
    for (int t = 0; t < 8; ++t) {
        float4 a = r4s[q * 8 + t], b = r4p[q * 8 + t];
        rs += (a.x + a.y) + (a.z + a.w);
        rp += (b.x + b.y) + (b.z + b.w);
    }
    #pragma unroll
    for (int t = 0; t < 4; ++t) {
        float4 a = c4s[q * 4 + t], b = c4p[q * 4 + t];
        cs += (a.x + a.y) + (a.z + a.w);
        cp += (b.x + b.y) + (b.z + b.w);
    }
    #pragma unroll
    for (int m = 1; m < 4; m <<= 1) {
        rs += __shfl_xor_sync(0xffffffffu, rs, m);
        rp += __shfl_xor_sync(0xffffffffu, rp, m);
        cs += __shfl_xor_sync(0xffffffffu, cs, m);
        cp += __shfl_xor_sync(0xffffffffu, cp, m);
    }
    if (q == 0) {
        float mp = rp / (rs + 1e-8f);
        float sc = cp / (cs + 1e-8f);
        float ans = 0.5f * (-logf(mp + 1e-8f)) + 0.5f * (-logf(sc + 1e-8f));
        if (isnan(ans) || isinf(ans)) ans = 0.0f;
        out[i] = ans;
    }
}

extern "C" void kernel_launch(void* const* d_in, const int* in_sizes, int n_in,
                              void* d_out, int out_size) {
    const float* z_mp = (const float*)d_in[0];
    const float* z_sc = (const float*)d_in[1];
    const float* W1   = (const float*)d_in[2];
    const float* b1   = (const float*)d_in[3];
    const float* W2   = (const float*)d_in[4];
    const float* b2   = (const float*)d_in[5];
    const int*   pos  = (const int*)d_in[6];
    float* out = (float*)d_out;

    cudaFuncSetAttribute(proj_kernel, cudaFuncAttributeMaxDynamicSharedMemorySize,
                         PROJ_SMEM_BYTES);
    cudaFuncSetAttribute(sim_kernel, cudaFuncAttributeMaxDynamicSharedMemorySize,
                         SIM_SMEM_BYTES);

    proj_kernel<<<dim3(128, 2), 256, PROJ_SMEM_BYTES>>>(z_mp, z_sc, W1, b1, W2, b2);
    sim_kernel<<<dim3(128, 64), 256, SIM_SMEM_BYTES>>>(pos);
    finish_kernel<<<128, 256>>>(out);
}

// round 9
// speedup vs baseline: 1.1213x; 1.1213x over previous
#include <cuda_runtime.h>
#include <cuda_bf16.h>
#include <cstdint>

#define NN 8192
#define INSZ 256
#define HID 128

// ---------------- device global scratch (allocation-free) ----------------
__device__ __align__(256) __nv_bfloat16 g_Ahi[NN * HID];
__device__ __align__(256) __nv_bfloat16 g_Bhi[NN * HID];
__device__ unsigned g_packed[NN * 256];      // pos bits: [r][c/32]
__device__ float g_rowS[NN * 128];           // [i][Jc]
__device__ float g_rowP[NN * 128];
__device__ float g_colS[NN * 64];            // [j][Ic]
__device__ float g_colP[NN * 64];

// ---------------- helpers ----------------
__device__ __forceinline__ uint32_t smem_u32(const void* p) {
    uint32_t a;
    asm("{ .reg .u64 t; cvta.to.shared.u64 t, %1; cvt.u32.u64 %0, t; }" : "=r"(a) : "l"(p));
    return a;
}
__device__ __forceinline__ float ex2f(float x) {
    float y; asm("ex2.approx.ftz.f32 %0, %1;" : "=f"(y) : "f"(x)); return y;
}
__device__ __forceinline__ void ldsm4(uint32_t a, uint32_t& r0, uint32_t& r1,
                                      uint32_t& r2, uint32_t& r3) {
    asm volatile("ldmatrix.sync.aligned.m8n8.x4.shared.b16 {%0,%1,%2,%3}, [%4];"
                 : "=r"(r0), "=r"(r1), "=r"(r2), "=r"(r3) : "r"(a));
}
__device__ __forceinline__ void mma16816(float* d, const uint32_t* a, const uint32_t* b) {
    asm volatile("mma.sync.aligned.m16n8k16.row.col.f32.bf16.bf16.f32 "
                 "{%0,%1,%2,%3}, {%4,%5,%6,%7}, {%8,%9}, {%0,%1,%2,%3};"
                 : "+f"(d[0]), "+f"(d[1]), "+f"(d[2]), "+f"(d[3])
                 : "r"(a[0]), "r"(a[1]), "r"(a[2]), "r"(a[3]), "r"(b[0]), "r"(b[1]));
}
__device__ __forceinline__ void cp16(uint32_t dst, const void* src) {
    asm volatile("cp.async.cg.shared.global [%0], [%1], 16;" :: "r"(dst), "l"(src));
}
__device__ __forceinline__ void cp_commit() {
    asm volatile("cp.async.commit_group;" ::: "memory");
}
__device__ __forceinline__ void cp_wait0() {
    asm volatile("cp.async.wait_group 0;" ::: "memory");
}
__device__ __forceinline__ void cp_wait1() {
    asm volatile("cp.async.wait_group 1;" ::: "memory");
}
__device__ __forceinline__ unsigned long long dup2(float a) {
    unsigned long long r; asm("mov.b64 %0, {%1, %1};" : "=l"(r) : "f"(a)); return r;
}
__device__ __forceinline__ void fma2(unsigned long long& d, unsigned long long a,
                                     unsigned long long b) {
    asm("fma.rn.f32x2 %0, %1, %2, %0;" : "+l"(d) : "l"(a), "l"(b));
}
__device__ __forceinline__ float2 unpk(unsigned long long v) {
    float2 r; asm("mov.b64 {%0, %1}, %2;" : "=f"(r.x), "=f"(r.y) : "l"(v)); return r;
}

// ---------------------------------------------------------------------------
// Kernel 1 (fused): blocks [0,256) = projection (double-buffered cp.async);
// blocks [256,8448) = pos bit-pack (int4 coalesced, DRAM-bound, overlaps).
// ---------------------------------------------------------------------------
#define ZS 68
#define HS 66
#define ZBUF_FLOATS (64 * ZS)      // 4352
#define WBUF_FLOATS (64 * 128)     // 8192
#define PREP_SMEM_FLOATS (2 * ZBUF_FLOATS + 2 * WBUF_FLOATS)   // 25088
#define PREP_SMEM_BYTES  (PREP_SMEM_FLOATS * 4)                // 100352

__global__ void __launch_bounds__(256, 2)
prep_kernel(const float* __restrict__ zA, const float* __restrict__ zB,
            const float* __restrict__ W1, const float* __restrict__ b1,
            const float* __restrict__ W2, const float* __restrict__ b2,
            const int* __restrict__ pos) {
    const int tid = threadIdx.x;

    if (blockIdx.x >= 256) {
        // ---------------- pack path (fast int4 + shfl-OR) ----------------
        int bid = blockIdx.x - 256;              // 0..8191
        int gw = bid * 8 + (tid >> 5);           // 0..65535
        int lane = tid & 31;
        int r = gw >> 3;
        int chunk = gw & 7;                      // 1024-col chunk
        const int4* base = (const int4*)(pos + (size_t)r * NN + chunk * 1024);
        unsigned wordsBase = (unsigned)r * 256 + chunk * 32;

        int4 v[8];
        #pragma unroll
        for (int t = 0; t < 8; ++t) v[t] = __ldcs(&base[t * 32 + lane]);

        #pragma unroll
        for (int t = 0; t < 8; ++t) {
            unsigned nib = (unsigned)(v[t].x != 0) | ((unsigned)(v[t].y != 0) << 1)
                         | ((unsigned)(v[t].z != 0) << 2) | ((unsigned)(v[t].w != 0) << 3);
            unsigned x = nib << ((lane & 7) * 4);
            x |= __shfl_xor_sync(0xffffffffu, x, 1);
            x |= __shfl_xor_sync(0xffffffffu, x, 2);
            x |= __shfl_xor_sync(0xffffffffu, x, 4);
            if ((lane & 7) == 0)
                g_packed[wordsBase + t * 4 + (lane >> 3)] = x;
        }
        return;
    }

    // ---------------- proj path ----------------
    const bool isA = (blockIdx.x < 128);
    const int blk = blockIdx.x & 127;
    const float* z = isA ? zA : zB;
    __nv_bfloat16* hiDst = isA ? g_Ahi : g_Bhi;

    extern __shared__ float sm[];
    float* zb[2] = { sm, sm + ZBUF_FLOATS };
    float* wb[2] = { sm + 2 * ZBUF_FLOATS, sm + 2 * ZBUF_FLOATS + WBUF_FLOATS };
    float* h_s = sm;                     // [128][HS] aliases z buffers after phase A
    const uint32_t sb = smem_u32(sm);
    const uint32_t zbo[2] = { sb, sb + ZBUF_FLOATS * 4 };
    const uint32_t wbo[2] = { sb + 2 * ZBUF_FLOATS * 4,
                              sb + (2 * ZBUF_FLOATS + WBUF_FLOATS) * 4 };

    const int tx = tid & 15, ty = tid >> 4;
    const int R0 = ty * 4, C0 = tx * 8;
    const float* zblk = z + (size_t)blk * 64 * INSZ;

    unsigned long long acc[4][4];
    #pragma unroll
    for (int i = 0; i < 4; ++i)
        #pragma unroll
        for (int jp = 0; jp < 4; ++jp) acc[i][jp] = 0ull;

    // stage chunk 0
    {
        #pragma unroll
        for (int it = 0; it < 4; ++it) {
            int e = it * 256 + tid;
            int r = e >> 4, k4 = (e & 15) * 4;
            cp16(zbo[0] + (r * ZS + k4) * 4, &zblk[r * INSZ + k4]);
        }
        #pragma unroll
        for (int it = 0; it < 8; ++it) {
            int e = it * 256 + tid;
            int k = e >> 5, c4 = (e & 31) * 4;
            cp16(wbo[0] + (k * 128 + c4) * 4, &W1[(size_t)k * HID + c4]);
        }
        cp_commit();
    }

    #pragma unroll
    for (int kc = 0; kc < 4; ++kc) {
        const int cur = kc & 1;
        if (kc < 3) {
            const int nxt = (kc + 1) & 1;
            #pragma unroll
            for (int it = 0; it < 4; ++it) {
                int e = it * 256 + tid;
                int r = e >> 4, k4 = (e & 15) * 4;
                cp16(zbo[nxt] + (r * ZS + k4) * 4, &zblk[r * INSZ + (kc + 1) * 64 + k4]);
            }
            #pragma unroll
            for (int it = 0; it < 8; ++it) {
                int e = it * 256 + tid;
                int k = e >> 5, c4 = (e & 31) * 4;
                cp16(wbo[nxt] + (k * 128 + c4) * 4,
                     &W1[(size_t)((kc + 1) * 64 + k) * HID + c4]);
            }
            cp_commit();
            cp_wait1();
        } else {
            cp_wait0();
        }
        __syncthreads();

        const float* z_s = zb[cur];
        const float* w_s = wb[cur];
        #pragma unroll 4
        for (int k = 0; k < 64; ++k) {
            ulonglong2 bb0 = *(const ulonglong2*)&w_s[k * 128 + C0];
            ulonglong2 bb1 = *(const ulonglong2*)&w_s[k * 128 + C0 + 4];
            #pragma unroll
            for (int i = 0; i < 4; ++i) {
                unsigned long long ad = dup2(z_s[(R0 + i) * ZS + k]);
                fma2(acc[i][0], ad, bb0.x);
                fma2(acc[i][1], ad, bb0.y);
                fma2(acc[i][2], ad, bb1.x);
                fma2(acc[i][3], ad, bb1.y);
            }
        }
        __syncthreads();   // before next iteration overwrites this buffer
    }

    float b1c[8];
    #pragma unroll
    for (int j = 0; j < 8; ++j) b1c[j] = b1[C0 + j];
    #pragma unroll
    for (int i = 0; i < 4; ++i) {
        #pragma unroll
        for (int jp = 0; jp < 4; ++jp) {
            float2 v = unpk(acc[i][jp]);
            float x0 = v.x + b1c[2 * jp];
            float x1 = v.y + b1c[2 * jp + 1];
            x0 = (x0 > 0.0f) ? x0 : (ex2f(fmaxf(x0, -30.0f) * 1.4426950408889634f) - 1.0f);
            x1 = (x1 > 0.0f) ? x1 : (ex2f(fmaxf(x1, -30.0f) * 1.4426950408889634f) - 1.0f);
            h_s[(C0 + 2 * jp)     * HS + R0 + i] = x0;
            h_s[(C0 + 2 * jp + 1) * HS + R0 + i] = x1;
        }
    }
    __syncthreads();

    #pragma unroll
    for (int i = 0; i < 4; ++i)
        #pragma unroll
        for (int jp = 0; jp < 4; ++jp) acc[i][jp] = 0ull;

    #pragma unroll 4
    for (int k = 0; k < 128; ++k) {
        ulonglong2 bb0 = *(const ulonglong2*)&W2[(size_t)k * HID + C0];
        ulonglong2 bb1 = *(const ulonglong2*)&W2[(size_t)k * HID + C0 + 4];
        #pragma unroll
        for (int i = 0; i < 4; ++i) {
            unsigned long long ad = dup2(h_s[k * HS + R0 + i]);
            fma2(acc[i][0], ad, bb0.x);
            fma2(acc[i][1], ad, bb0.y);
            fma2(acc[i][2], ad, bb1.x);
            fma2(acc[i][3], ad, bb1.y);
        }
    }

    float b2c[8];
    #pragma unroll
    for (int j = 0; j < 8; ++j) b2c[j] = b2[C0 + j];

    float x[4][8], ss[4];
    #pragma unroll
    for (int i = 0; i < 4; ++i) {
        float s = 0.0f;
        #pragma unroll
        for (int jp = 0; jp < 4; ++jp) {
            float2 v = unpk(acc[i][jp]);
            float x0 = v.x + b2c[2 * jp];
            float x1 = v.y + b2c[2 * jp + 1];
            x[i][2 * jp] = x0; x[i][2 * jp + 1] = x1;
            s = fmaf(x0, x0, s); s = fmaf(x1, x1, s);
        }
        ss[i] = s;
    }
    #pragma unroll
    for (int m = 1; m < 16; m <<= 1)
        #pragma unroll
        for (int i = 0; i < 4; ++i)
            ss[i] += __shfl_xor_sync(0xffffffffu, ss[i], m);

    const float scl = isA ? 7.2134752044448170f : 1.0f;   // 5 * log2(e) on A
    union { __nv_bfloat16 b[8]; uint4 u; } hv;
    #pragma unroll
    for (int i = 0; i < 4; ++i) {
        float inv = scl / fmaxf(sqrtf(ss[i]), 1e-12f);
        int gRow = blk * 64 + R0 + i;
        #pragma unroll
        for (int j = 0; j < 8; ++j)
            hv.b[j] = __float2bfloat16(x[i][j] * inv);
        *(uint4*)&hiDst[(size_t)gRow * HID + C0] = hv.u;
    }
}

// ---------------------------------------------------------------------------
// Kernel 2: fused sim tile 128(M) x 64(N), single bf16 pass, 3 CTAs/SM.
// (R7 form: packed pos bits preloaded to smem.)
// ---------------------------------------------------------------------------
#define SM_A0 0
#define SM_B0 32768
#define SM_POSR 49152
#define SM_POSC 50176
#define SM_ROWS 0
#define SM_ROWP 1024
#define SM_COLS 2048
#define SM_COLP 3072
#define SIM_SMEM_BYTES 51200

__global__ void __launch_bounds__(256, 3) sim_kernel() {
    const int J = blockIdx.x, I = blockIdx.y;
    extern __shared__ char smc[];
    const uint32_t sb = smem_u32(smc);
    const int tid = threadIdx.x;
    const int lane = tid & 31, wid = tid >> 5;
    const int wm = wid & 3, wn = wid >> 2;

    // ---- async-load operand tiles (swizzled: chunk c -> c ^ (r&7)) ----
    {
        const uint4* srcA0 = (const uint4*)(g_Ahi + (size_t)I * 128 * HID);
        const uint4* srcB0 = (const uint4*)(g_Bhi + (size_t)J * 64 * HID);
        #pragma unroll
        for (int it = 0; it < 8; ++it) {
            int e = it * 256 + tid;
            int r = e >> 4, c = e & 15;
            uint32_t so = r * 256 + ((c ^ (r & 7)) << 4);
            cp16(sb + SM_A0 + so, srcA0 + e);
            if (it < 4) cp16(sb + SM_B0 + so, srcB0 + e);
        }
    }
    unsigned* posR = (unsigned*)(smc + SM_POSR);   // [128 rows][2 words]
    unsigned* posC = (unsigned*)(smc + SM_POSC);   // [64 cols][4 words]
    posR[tid] = g_packed[(size_t)(I * 128 + (tid >> 1)) * 256 + J * 2 + (tid & 1)];
    posC[tid] = g_packed[(size_t)(J * 64 + (tid >> 2)) * 256 + I * 4 + (tid & 3)];
    cp_commit(); cp_wait0();
    __syncthreads();

    // ---- MMA mainloop (single pass) ----
    float d[2][4][4];
    #pragma unroll
    for (int mt = 0; mt < 2; ++mt)
        #pragma unroll
        for (int nt = 0; nt < 4; ++nt)
            #pragma unroll
            for (int k = 0; k < 4; ++k) d[mt][nt][k] = 0.0f;

    const uint32_t aB0 = sb + SM_A0, bB = sb + SM_B0;

    #pragma unroll
    for (int ks = 0; ks < 8; ++ks) {
        uint32_t bf[4][2];
        #pragma unroll
        for (int np = 0; np < 2; ++np) {
            int l = lane & 7, g = lane >> 3;
            int row = wn * 32 + np * 16 + ((g >> 1) << 3) + l;
            int ch  = ks * 2 + (g & 1);
            ldsm4(bB + row * 256 + ((ch ^ (row & 7)) << 4),
                  bf[2 * np][0], bf[2 * np][1], bf[2 * np + 1][0], bf[2 * np + 1][1]);
        }
        uint32_t af0[2][4];
        #pragma unroll
        for (int mt = 0; mt < 2; ++mt) {
            int row = wm * 32 + mt * 16 + (lane & 15);
            int ch  = ks * 2 + (lane >> 4);
            uint32_t so = row * 256 + ((ch ^ (row & 7)) << 4);
            ldsm4(aB0 + so, af0[mt][0], af0[mt][1], af0[mt][2], af0[mt][3]);
        }
        #pragma unroll
        for (int mt = 0; mt < 2; ++mt)
            #pragma unroll
            for (int nt = 0; nt < 4; ++nt)
                mma16816(d[mt][nt], af0[mt], bf[nt]);
    }
    __syncthreads();

    // ---- epilogue ----
    #pragma unroll
    for (int mt = 0; mt < 2; ++mt)
        #pragma unroll
        for (int nt = 0; nt < 4; ++nt)
            #pragma unroll
            for (int k = 0; k < 4; ++k)
                d[mt][nt][k] = ex2f(d[mt][nt][k]);

    float* rowSsm = (float*)(smc + SM_ROWS);
    float* rowPsm = (float*)(smc + SM_ROWP);
    float* colSsm = (float*)(smc + SM_COLS);
    float* colPsm = (float*)(smc + SM_COLP);

    #pragma unroll
    for (int mt = 0; mt < 2; ++mt) {
        #pragma unroll
        for (int h = 0; h < 2; ++h) {
            int iloc = wm * 32 + mt * 16 + h * 8 + (lane >> 2);
            unsigned w = posR[iloc * 2 + wn];
            float s = 0.0f, p = 0.0f;
            #pragma unroll
            for (int nt = 0; nt < 4; ++nt)
                #pragma unroll
                for (int b = 0; b < 2; ++b) {
                    float e = d[mt][nt][h * 2 + b];
                    s += e;
                    int bit = nt * 8 + (lane & 3) * 2 + b;
                    if ((w >> bit) & 1u) p += e;
                }
            s += __shfl_xor_sync(0xffffffffu, s, 1);
            s += __shfl_xor_sync(0xffffffffu, s, 2);
            p += __shfl_xor_sync(0xffffffffu, p, 1);
            p += __shfl_xor_sync(0xffffffffu, p, 2);
            if ((lane & 3) == 0) {
                rowSsm[wn * 128 + iloc] = s;
                rowPsm[wn * 128 + iloc] = p;
            }
        }
    }

    #pragma unroll
    for (int nt = 0; nt < 4; ++nt) {
        #pragma unroll
        for (int b = 0; b < 2; ++b) {
            int jloc = wn * 32 + nt * 8 + (lane & 3) * 2 + b;
            unsigned w = posC[jloc * 4 + wm];
            float s = 0.0f, p = 0.0f;
            #pragma unroll
            for (int mt = 0; mt < 2; ++mt)
                #pragma unroll
                for (int h = 0; h < 2; ++h) {
                    float e = d[mt][nt][h * 2 + b];
                    s += e;
                    int bit = mt * 16 + h * 8 + (lane >> 2);
                    if ((w >> bit) & 1u) p += e;
                }
            s += __shfl_xor_sync(0xffffffffu, s, 4);
            s += __shfl_xor_sync(0xffffffffu, s, 8);
            s += __shfl_xor_sync(0xffffffffu, s, 16);
            p += __shfl_xor_sync(0xffffffffu, p, 4);
            p += __shfl_xor_sync(0xffffffffu, p, 8);
            p += __shfl_xor_sync(0xffffffffu, p, 16);
            if ((lane >> 2) == 0) {
                colSsm[wm * 64 + jloc] = s;
                colPsm[wm * 64 + jloc] = p;
            }
        }
    }
    __syncthreads();

    if (tid < 128) {
        float rs = rowSsm[tid] + rowSsm[128 + tid];
        float rp = rowPsm[tid] + rowPsm[128 + tid];
        g_rowS[(size_t)(I * 128 + tid) * 128 + J] = rs;
        g_rowP[(size_t)(I * 128 + tid) * 128 + J] = rp;
    } else if (tid < 192) {
        int j = tid - 128;
        float cs = colSsm[j] + colSsm[64 + j] + colSsm[128 + j] + colSsm[192 + j];
        float cp = colPsm[j] + colPsm[64 + j] + colPsm[128 + j] + colPsm[192 + j];
        g_colS[(size_t)(J * 64 + j) * 64 + I] = cs;
        g_colP[(size_t)(J * 64 + j) * 64 + I] = cp;
    }
}

// ---------------------------------------------------------------------------
// Kernel 3: final reduction, 4 threads per row (deterministic, fixed split)
// ---------------------------------------------------------------------------
__global__ void __launch_bounds__(256) finish_kernel(float* __restrict__ out) {
    int g = blockIdx.x * 256 + threadIdx.x;   // grid 128 x 256 = 32768
    int i = g >> 2, q = g & 3;
    const float4* r4s = (const float4*)&g_rowS[(size_t)i * 128];
    const float4* r4p = (const float4*)&g_rowP[(size_t)i * 128];
    const float4* c4s = (const float4*)&g_colS[(size_t)i * 64];
    const float4* c4p = (const float4*)&g_colP[(size_t)i * 64];
    float rs = 0.0f, rp = 0.0f, cs = 0.0f, cp = 0.0f;
    #pragma unroll
    for (int t = 0; t < 8; ++t) {
        float4 a = r4s[q * 8 + t], b = r4p[q * 8 + t];
        rs += (a.x + a.y) + (a.z + a.w);
        rp += (b.x + b.y) + (b.z + b.w);
    }
    #pragma unroll
    for (int t = 0; t < 4; ++t) {
        float4 a = c4s[q * 4 + t], b = c4p[q * 4 + t];
        cs += (a.x + a.y) + (a.z + a.w);
        cp += (b.x + b.y) + (b.z + b.w);
    }
    #pragma unroll
    for (int m = 1; m < 4; m <<= 1) {
        rs += __shfl_xor_sync(0xffffffffu, rs, m);
        rp += __shfl_xor_sync(0xffffffffu, rp, m);
        cs += __shfl_xor_sync(0xffffffffu, cs, m);
        cp += __shfl_xor_sync(0xffffffffu, cp, m);
    }
    if (q == 0) {
        float mp = rp / (rs + 1e-8f);
        float sc = cp / (cs + 1e-8f);
        float ans = 0.5f * (-logf(mp + 1e-8f)) + 0.5f * (-logf(sc + 1e-8f));
        if (isnan(ans) || isinf(ans)) ans = 0.0f;
        out[i] = ans;
    }
}

extern "C" void kernel_launch(void* const* d_in, const int* in_sizes, int n_in,
                              void* d_out, int out_size) {
    const float* z_mp = (const float*)d_in[0];
    const float* z_sc = (const float*)d_in[1];
    const float* W1   = (const float*)d_in[2];
    const float* b1   = (const float*)d_in[3];
    const float* W2   = (const float*)d_in[4];
    const float* b2   = (const float*)d_in[5];
    const int*   pos  = (const int*)d_in[6];
    float* out = (float*)d_out;

    cudaFuncSetAttribute(prep_kernel, cudaFuncAttributeMaxDynamicSharedMemorySize,
                         PREP_SMEM_BYTES);
    cudaFuncSetAttribute(sim_kernel, cudaFuncAttributeMaxDynamicSharedMemorySize,
                         SIM_SMEM_BYTES);

    prep_kernel<<<8448, 256, PREP_SMEM_BYTES>>>(z_mp, z_sc, W1, b1, W2, b2, pos);
    sim_kernel<<<dim3(128, 64), 256, SIM_SMEM_BYTES>>>();
    finish_kernel<<<128, 256>>>(out);
}